// round 14
// baseline (speedup 1.0000x reference)
#include <cuda_runtime.h>
#include <cstdint>

// ============================================================================
// out[16384,4096] = x @ ((W_int - zp)*scale)^T + bias       (sm_103, no tcgen05)
// tf32 mma.sync HMMA. W ints exact in tf32 (raw f32 bits); x pre-rounded (rna).
// R14: CTA tile 128x128, 4 warps of 64x64, 128 threads -> 2 CTAs/SM
// (two independent barrier domains hide each other's CP_WAIT/syncthreads
//  convoys — the mechanism that made R9 the best run — combined with the
//  low-traffic 64x64 warp tile from R12/13). 3-stage cp.async, XOR swizzle,
// double-buffered ldmatrix fragments.
// Epilogue: out = scale*G - (scale*zp)*rowsum(x) + bias.
// ============================================================================

#define M_TOTAL 16384
#define N_TOTAL 4096
#define K_TOTAL 4096
#define BM 128
#define BN 128
#define BK 32
#define NST 3
#define NITERS (K_TOTAL / BK)          // 128
#define ASTAGE 16384                   // A: 128 rows x 128B
#define STAGE_BYTES 32768              // A + B
#define SMEM_BYTES (NST * STAGE_BYTES) // 98304 -> 2 CTAs/SM (192KB)

__device__ float g_xa[(size_t)M_TOTAL * K_TOTAL];   // tf32-rounded x
__device__ float g_rs[M_TOTAL];                     // per-row sum of x

#define CP16(sa, g) \
    asm volatile("cp.async.cg.shared.global [%0], [%1], 16;" :: "r"(sa), "l"(g))
#define CP_COMMIT() asm volatile("cp.async.commit_group;" ::: "memory")
#define CP_WAIT(n)  asm volatile("cp.async.wait_group %0;" :: "n"(n) : "memory")

__device__ __forceinline__ uint32_t f2tf32(float f) {
    uint32_t u;
    asm("cvt.rna.tf32.f32 %0, %1;" : "=r"(u) : "f"(f));
    return u;
}

#define LDSM4(r, addr) \
    asm volatile("ldmatrix.sync.aligned.m8n8.x4.shared.b16 {%0,%1,%2,%3}, [%4];" \
                 : "=r"((r)[0]), "=r"((r)[1]), "=r"((r)[2]), "=r"((r)[3]) \
                 : "r"(addr))

#define MMA_TF32(d, a, b0, b1)                                                 \
    asm volatile("mma.sync.aligned.m16n8k8.row.col.f32.tf32.tf32.f32 "         \
                 "{%0,%1,%2,%3},{%4,%5,%6,%7},{%8,%9},{%0,%1,%2,%3};"          \
                 : "+f"((d)[0]), "+f"((d)[1]), "+f"((d)[2]), "+f"((d)[3])      \
                 : "r"((a)[0]), "r"((a)[1]), "r"((a)[2]), "r"((a)[3]),         \
                   "r"(b0), "r"(b1))

// ============================================================================
// Kernel 1: x -> tf32-rounded copy + per-row sum. One warp per row.
// ============================================================================
__global__ void __launch_bounds__(256) prep_kernel(const float* __restrict__ x) {
    int row = blockIdx.x * 8 + (threadIdx.x >> 5);
    int lane = threadIdx.x & 31;
    const float4* xr = reinterpret_cast<const float4*>(x + (size_t)row * K_TOTAL);
    float4* xo = reinterpret_cast<float4*>(g_xa + (size_t)row * K_TOTAL);
    float s = 0.f;
#pragma unroll 4
    for (int i = lane; i < K_TOTAL / 4; i += 32) {
        float4 v = xr[i];
        s += (v.x + v.y) + (v.z + v.w);
        float4 o;
        o.x = __uint_as_float(f2tf32(v.x));
        o.y = __uint_as_float(f2tf32(v.y));
        o.z = __uint_as_float(f2tf32(v.z));
        o.w = __uint_as_float(f2tf32(v.w));
        xo[i] = o;
    }
#pragma unroll
    for (int o = 16; o > 0; o >>= 1) s += __shfl_xor_sync(0xffffffffu, s, o);
    if (lane == 0) g_rs[row] = s;
}

// ============================================================================
// Kernel 2: tf32 GEMM, 128x128x32 tile, 4 warps of 64x64, 3-stage pipeline,
// 2 CTAs/SM, double-buffered register fragments.
// ============================================================================
__global__ void __launch_bounds__(128, 2) gemm_kernel(
    const float* __restrict__ w,
    const float* __restrict__ scales, const float* __restrict__ zp,
    const float* __restrict__ bias, float* __restrict__ out) {
    extern __shared__ float smem[];
    const uint32_t sbase = (uint32_t)__cvta_generic_to_shared(smem);
    const int tid = threadIdx.x;
    const int lane = tid & 31;
    const int wid = tid >> 5;
    const int warp_m = wid >> 1;            // 0..1 (64 rows)
    const int warp_n = wid & 1;             // 0..1 (64 cols)
    const int m0 = blockIdx.y * BM;
    const int n0 = blockIdx.x * BN;

    // ---- loader: thread tid owns row tid of A and of B, 8 chunks each ----
    const float* gA = g_xa + (size_t)(m0 + tid) * K_TOTAL;
    const float* gB = w + (size_t)(n0 + tid) * K_TOTAL;
    uint32_t soff[8];
#pragma unroll
    for (int i = 0; i < 8; i++)
        soff[i] = (uint32_t)(tid * 128 + ((i ^ (tid & 7)) << 4));

    // ---- ldmatrix per-lane addressing (proven pattern) ----
    const uint32_t sa = lane & 7;
    const uint32_t c0a = lane >> 4;          // A chunk parity
    const uint32_t c0b = (lane >> 3) & 1;    // B chunk parity
    uint32_t aoff[4];
#pragma unroll
    for (int mt = 0; mt < 4; mt++) {
        int rowA = warp_m * 64 + mt * 16 + ((lane >> 3) & 1) * 8 + (lane & 7);
        aoff[mt] = (uint32_t)(rowA * 128);
    }
    uint32_t boff[4];
#pragma unroll
    for (int bg = 0; bg < 4; bg++) {
        int rowB = warp_n * 64 + bg * 16 + ((lane >> 4) & 1) * 8 + (lane & 7);
        boff[bg] = (uint32_t)(rowB * 128);
    }

    float acc[4][8][4];                      // 128 regs: 64x64 warp tile
#pragma unroll
    for (int i = 0; i < 4; i++)
#pragma unroll
        for (int j = 0; j < 8; j++)
#pragma unroll
            for (int k = 0; k < 4; k++) acc[i][j][k] = 0.f;

    // ---- prologue: fill NST-1 = 2 stages ----
#pragma unroll
    for (int p = 0; p < NST - 1; p++) {
        uint32_t As = sbase + p * STAGE_BYTES;
        uint32_t Bs = As + ASTAGE;
        int kk = p * BK;
#pragma unroll
        for (int i = 0; i < 8; i++) {
            CP16(As + soff[i], gA + kk + i * 4);
            CP16(Bs + soff[i], gB + kk + i * 4);
        }
        CP_COMMIT();
    }

    uint32_t a[2][4][4], b[2][4][4];         // double-buffered fragments

    int sidx = 0;
    for (int it = 0; it < NITERS; it++) {
        CP_WAIT(NST - 2);
        __syncthreads();

        const uint32_t Ab = sbase + sidx * STAGE_BYTES;
        const uint32_t Bb = Ab + ASTAGE;

        // phase-0 fragments first: MMAs can start immediately
        {
            const uint32_t csw  = (c0a ^ sa) << 4;
            const uint32_t cswb = (c0b ^ sa) << 4;
#pragma unroll
            for (int mt = 0; mt < 4; mt++) LDSM4(a[0][mt], Ab + aoff[mt] + csw);
#pragma unroll
            for (int bg = 0; bg < 4; bg++) LDSM4(b[0][bg], Bb + boff[bg] + cswb);
        }

        // issue next-stage loads (latency budget: 2 stages ahead)
        int nidx = sidx + (NST - 1); if (nidx >= NST) nidx -= NST;
        int nxt = it + (NST - 1);
        if (nxt < NITERS) {
            uint32_t As = sbase + nidx * STAGE_BYTES;
            uint32_t Bs = As + ASTAGE;
            int kk = nxt * BK;
#pragma unroll
            for (int i = 0; i < 8; i++) {
                CP16(As + soff[i], gA + kk + i * 4);
                CP16(Bs + soff[i], gB + kk + i * 4);
            }
        }
        CP_COMMIT();

#pragma unroll
        for (int ks = 0; ks < 4; ks++) {
            const int cur = ks & 1;
            if (ks < 3) {                    // prefetch phase ks+1 fragments
                const uint32_t csw  = (((uint32_t)(2 * (ks + 1)) + c0a) ^ sa) << 4;
                const uint32_t cswb = (((uint32_t)(2 * (ks + 1)) + c0b) ^ sa) << 4;
#pragma unroll
                for (int mt = 0; mt < 4; mt++)
                    LDSM4(a[cur ^ 1][mt], Ab + aoff[mt] + csw);
#pragma unroll
                for (int bg = 0; bg < 4; bg++)
                    LDSM4(b[cur ^ 1][bg], Bb + boff[bg] + cswb);
            }
#pragma unroll
            for (int mt = 0; mt < 4; mt++)
#pragma unroll
                for (int nt = 0; nt < 8; nt++)
                    MMA_TF32(acc[mt][nt], a[cur][mt], b[cur][nt >> 1][(nt & 1) * 2],
                             b[cur][nt >> 1][(nt & 1) * 2 + 1]);
        }
        sidx++; if (sidx >= NST) sidx = 0;
    }

    // ---- epilogue: out = acc*scale - (scale*zp)*rowsum + bias ----
    const int g = lane >> 2;
    const int t = lane & 3;
    float rs[8];
#pragma unroll
    for (int mt = 0; mt < 4; mt++) {
        rs[mt * 2 + 0] = g_rs[m0 + warp_m * 64 + mt * 16 + g];
        rs[mt * 2 + 1] = g_rs[m0 + warp_m * 64 + mt * 16 + g + 8];
    }
#pragma unroll
    for (int nt = 0; nt < 8; nt++) {
        int n = n0 + warp_n * 64 + nt * 8 + t * 2;
        float s0 = __ldg(scales + n),     s1 = __ldg(scales + n + 1);
        float z0 = s0 * __ldg(zp + n),    z1 = s1 * __ldg(zp + n + 1);
        float b0 = __ldg(bias + n),       b1 = __ldg(bias + n + 1);
#pragma unroll
        for (int mt = 0; mt < 4; mt++) {
#pragma unroll
            for (int h = 0; h < 2; h++) {
                int row = m0 + warp_m * 64 + mt * 16 + g + h * 8;
                float r = rs[mt * 2 + h];
                float2 v;
                v.x = fmaf(acc[mt][nt][h * 2 + 0], s0, fmaf(-z0, r, b0));
                v.y = fmaf(acc[mt][nt][h * 2 + 1], s1, fmaf(-z1, r, b1));
                *reinterpret_cast<float2*>(out + (size_t)row * N_TOTAL + n) = v;
            }
        }
    }
}

// ============================================================================
// Launch
// ============================================================================
extern "C" void kernel_launch(void* const* d_in, const int* in_sizes, int n_in,
                              void* d_out, int out_size) {
    const float* x      = (const float*)d_in[0];
    const float* wf     = (const float*)d_in[1];
    const float* scales = (const float*)d_in[2];
    const float* zp     = (const float*)d_in[3];
    const float* bias   = (const float*)d_in[4];
    float* out = (float*)d_out;

    prep_kernel<<<M_TOTAL / 8, 256>>>(x);

    cudaFuncSetAttribute(gemm_kernel, cudaFuncAttributeMaxDynamicSharedMemorySize,
                         SMEM_BYTES);
    dim3 grid(N_TOTAL / BN, M_TOTAL / BM, 1);   // n-fastest: W slab L2-resident
    gemm_kernel<<<grid, 128, SMEM_BYTES>>>(wf, scales, zp, bias, out);
}

// round 17
// speedup vs baseline: 1.2638x; 1.2638x over previous
#include <cuda_runtime.h>
#include <cstdint>

// ============================================================================
// out[16384,4096] = x @ ((W_int - zp)*scale)^T + bias       (sm_103, no tcgen05)
// tf32 mma.sync HMMA (legacy peak ~512 MAC/cyc/SM measured). W ints exact in
// tf32 (raw f32 bits); x pre-rounded (rna) in prepass.
// R15: latency-bound fix -> MORE WARPS. 32x32 warp tiles (~80 regs) allow
// 3 CTAs x 256 threads = 24 warps/SM across 3 barrier domains.
// CTA tile 64x128, 8 warps (2x4), NST=3 cp.async, XOR-swizzled 128B rows,
// proven R9 ldmatrix addressing. Epilogue: scale*G - (scale*zp)*rowsum + bias.
// ============================================================================

#define M_TOTAL 16384
#define N_TOTAL 4096
#define K_TOTAL 4096
#define BM 64
#define BN 128
#define BK 32
#define NST 3
#define NITERS (K_TOTAL / BK)          // 128
#define ASTAGE 8192                    // A: 64 rows x 128B
#define STAGE_BYTES 24576              // A 8KB + B 16KB
#define SMEM_BYTES (NST * STAGE_BYTES) // 73728 -> 3 CTAs/SM (216KB)

__device__ float g_xa[(size_t)M_TOTAL * K_TOTAL];   // tf32-rounded x
__device__ float g_rs[M_TOTAL];                     // per-row sum of x

#define CP16(sa, g) \
    asm volatile("cp.async.cg.shared.global [%0], [%1], 16;" :: "r"(sa), "l"(g))
#define CP_COMMIT() asm volatile("cp.async.commit_group;" ::: "memory")
#define CP_WAIT(n)  asm volatile("cp.async.wait_group %0;" :: "n"(n) : "memory")

__device__ __forceinline__ uint32_t f2tf32(float f) {
    uint32_t u;
    asm("cvt.rna.tf32.f32 %0, %1;" : "=r"(u) : "f"(f));
    return u;
}

#define LDSM4(r, addr) \
    asm volatile("ldmatrix.sync.aligned.m8n8.x4.shared.b16 {%0,%1,%2,%3}, [%4];" \
                 : "=r"((r)[0]), "=r"((r)[1]), "=r"((r)[2]), "=r"((r)[3]) \
                 : "r"(addr))

#define MMA_TF32(d, a, b0, b1)                                                 \
    asm volatile("mma.sync.aligned.m16n8k8.row.col.f32.tf32.tf32.f32 "         \
                 "{%0,%1,%2,%3},{%4,%5,%6,%7},{%8,%9},{%0,%1,%2,%3};"          \
                 : "+f"((d)[0]), "+f"((d)[1]), "+f"((d)[2]), "+f"((d)[3])      \
                 : "r"((a)[0]), "r"((a)[1]), "r"((a)[2]), "r"((a)[3]),         \
                   "r"(b0), "r"(b1))

// ============================================================================
// Kernel 1: x -> tf32-rounded copy + per-row sum. One warp per row.
// ============================================================================
__global__ void __launch_bounds__(256) prep_kernel(const float* __restrict__ x) {
    int row = blockIdx.x * 8 + (threadIdx.x >> 5);
    int lane = threadIdx.x & 31;
    const float4* xr = reinterpret_cast<const float4*>(x + (size_t)row * K_TOTAL);
    float4* xo = reinterpret_cast<float4*>(g_xa + (size_t)row * K_TOTAL);
    float s = 0.f;
#pragma unroll 4
    for (int i = lane; i < K_TOTAL / 4; i += 32) {
        float4 v = xr[i];
        s += (v.x + v.y) + (v.z + v.w);
        float4 o;
        o.x = __uint_as_float(f2tf32(v.x));
        o.y = __uint_as_float(f2tf32(v.y));
        o.z = __uint_as_float(f2tf32(v.z));
        o.w = __uint_as_float(f2tf32(v.w));
        xo[i] = o;
    }
#pragma unroll
    for (int o = 16; o > 0; o >>= 1) s += __shfl_xor_sync(0xffffffffu, s, o);
    if (lane == 0) g_rs[row] = s;
}

// ============================================================================
// Kernel 2: tf32 GEMM, 64x128x32 CTA tile, 8 warps of 32x32, 3 CTAs/SM.
// ============================================================================
__global__ void __launch_bounds__(256, 3) gemm_kernel(
    const float* __restrict__ w,
    const float* __restrict__ scales, const float* __restrict__ zp,
    const float* __restrict__ bias, float* __restrict__ out) {
    extern __shared__ float smem[];
    const uint32_t sbase = (uint32_t)__cvta_generic_to_shared(smem);
    const int tid = threadIdx.x;
    const int lane = tid & 31;
    const int wid = tid >> 5;
    const int warp_m = wid >> 2;            // 0..1 (32 rows each)
    const int warp_n = wid & 3;             // 0..3 (32 cols each)
    const int m0 = blockIdx.y * BM;
    const int n0 = blockIdx.x * BN;

    // ---- loader: A 64 rows (2 chunks/thread), B 128 rows (4 chunks/thread) --
    const int arow = tid >> 2;              // 0..63
    const int acb  = (tid & 3) * 2;         // chunk base 0,2,4,6
    const int brow = tid >> 1;              // 0..127
    const int bcb  = (tid & 1) * 4;         // chunk base 0,4
    const float* gA = g_xa + (size_t)(m0 + arow) * K_TOTAL;
    const float* gB = w + (size_t)(n0 + brow) * K_TOTAL;
    uint32_t soffA[2], soffB[4];
#pragma unroll
    for (int i = 0; i < 2; i++)
        soffA[i] = (uint32_t)(arow * 128 + (((acb + i) ^ (arow & 7)) << 4));
#pragma unroll
    for (int i = 0; i < 4; i++)
        soffB[i] = (uint32_t)(brow * 128 + (((bcb + i) ^ (brow & 7)) << 4));

    // ---- ldmatrix per-lane addressing (proven R9 pattern) ----
    const uint32_t sa = lane & 7;
    const uint32_t c0a = lane >> 4;          // A chunk parity
    const uint32_t c0b = (lane >> 3) & 1;    // B chunk parity
    uint32_t aoff[2];
#pragma unroll
    for (int mt = 0; mt < 2; mt++) {
        int rowA = warp_m * 32 + mt * 16 + ((lane >> 3) & 1) * 8 + (lane & 7);
        aoff[mt] = (uint32_t)(rowA * 128);
    }
    uint32_t boff[2];
#pragma unroll
    for (int bg = 0; bg < 2; bg++) {
        int rowB = warp_n * 32 + bg * 16 + ((lane >> 4) & 1) * 8 + (lane & 7);
        boff[bg] = (uint32_t)(rowB * 128);
    }

    float acc[2][4][4];                      // 32 regs: 32x32 warp tile
#pragma unroll
    for (int i = 0; i < 2; i++)
#pragma unroll
        for (int j = 0; j < 4; j++)
#pragma unroll
            for (int k = 0; k < 4; k++) acc[i][j][k] = 0.f;

    // ---- prologue: fill 2 of 3 stages ----
#pragma unroll
    for (int p = 0; p < NST - 1; p++) {
        uint32_t As = sbase + p * STAGE_BYTES;
        uint32_t Bs = As + ASTAGE;
        int kk = p * BK;
#pragma unroll
        for (int i = 0; i < 2; i++) CP16(As + soffA[i], gA + kk + (acb + i) * 4);
#pragma unroll
        for (int i = 0; i < 4; i++) CP16(Bs + soffB[i], gB + kk + (bcb + i) * 4);
        CP_COMMIT();
    }

    int sidx = 0;
    for (int it = 0; it < NITERS; it++) {
        CP_WAIT(1);
        __syncthreads();

        // issue next-stage loads first (2-ahead latency budget)
        int nidx = sidx + (NST - 1); if (nidx >= NST) nidx -= NST;
        int nxt = it + (NST - 1);
        if (nxt < NITERS) {
            uint32_t As = sbase + nidx * STAGE_BYTES;
            uint32_t Bs = As + ASTAGE;
            int kk = nxt * BK;
#pragma unroll
            for (int i = 0; i < 2; i++) CP16(As + soffA[i], gA + kk + (acb + i) * 4);
#pragma unroll
            for (int i = 0; i < 4; i++) CP16(Bs + soffB[i], gB + kk + (bcb + i) * 4);
        }
        CP_COMMIT();

        const uint32_t Ab = sbase + sidx * STAGE_BYTES;
        const uint32_t Bb = Ab + ASTAGE;
#pragma unroll
        for (int ks = 0; ks < 4; ks++) {
            const uint32_t csw  = (((uint32_t)(2 * ks) + c0a) ^ sa) << 4;
            const uint32_t cswb = (((uint32_t)(2 * ks) + c0b) ^ sa) << 4;
            uint32_t a[2][4];
#pragma unroll
            for (int mt = 0; mt < 2; mt++) LDSM4(a[mt], Ab + aoff[mt] + csw);
            uint32_t b[2][4];
#pragma unroll
            for (int bg = 0; bg < 2; bg++) LDSM4(b[bg], Bb + boff[bg] + cswb);
#pragma unroll
            for (int mt = 0; mt < 2; mt++)
#pragma unroll
                for (int nt = 0; nt < 4; nt++)
                    MMA_TF32(acc[mt][nt], a[mt], b[nt >> 1][(nt & 1) * 2],
                             b[nt >> 1][(nt & 1) * 2 + 1]);
        }
        sidx++; if (sidx >= NST) sidx = 0;
    }

    // ---- epilogue: out = acc*scale - (scale*zp)*rowsum + bias ----
    const int g = lane >> 2;
    const int t = lane & 3;
    float rs[4];
#pragma unroll
    for (int mt = 0; mt < 2; mt++) {
        rs[mt * 2 + 0] = g_rs[m0 + warp_m * 32 + mt * 16 + g];
        rs[mt * 2 + 1] = g_rs[m0 + warp_m * 32 + mt * 16 + g + 8];
    }
#pragma unroll
    for (int nt = 0; nt < 4; nt++) {
        int n = n0 + warp_n * 32 + nt * 8 + t * 2;
        float s0 = __ldg(scales + n),     s1 = __ldg(scales + n + 1);
        float z0 = s0 * __ldg(zp + n),    z1 = s1 * __ldg(zp + n + 1);
        float b0 = __ldg(bias + n),       b1 = __ldg(bias + n + 1);
#pragma unroll
        for (int mt = 0; mt < 2; mt++) {
#pragma unroll
            for (int h = 0; h < 2; h++) {
                int row = m0 + warp_m * 32 + mt * 16 + g + h * 8;
                float r = rs[mt * 2 + h];
                float2 v;
                v.x = fmaf(acc[mt][nt][h * 2 + 0], s0, fmaf(-z0, r, b0));
                v.y = fmaf(acc[mt][nt][h * 2 + 1], s1, fmaf(-z1, r, b1));
                *reinterpret_cast<float2*>(out + (size_t)row * N_TOTAL + n) = v;
            }
        }
    }
}

// ============================================================================
// Launch
// ============================================================================
extern "C" void kernel_launch(void* const* d_in, const int* in_sizes, int n_in,
                              void* d_out, int out_size) {
    const float* x      = (const float*)d_in[0];
    const float* wf     = (const float*)d_in[1];
    const float* scales = (const float*)d_in[2];
    const float* zp     = (const float*)d_in[3];
    const float* bias   = (const float*)d_in[4];
    float* out = (float*)d_out;

    prep_kernel<<<M_TOTAL / 8, 256>>>(x);

    cudaFuncSetAttribute(gemm_kernel, cudaFuncAttributeMaxDynamicSharedMemorySize,
                         SMEM_BYTES);
    dim3 grid(N_TOTAL / BN, M_TOTAL / BM, 1);   // n-fastest: A group + W L2-resident
    gemm_kernel<<<grid, 256, SMEM_BYTES>>>(wf, scales, zp, bias, out);
}